// round 3
// baseline (speedup 1.0000x reference)
#include <cuda_runtime.h>
#include <cuda_bf16.h>

// One thread per EDGE. Each thread:
//   1 x src load (4B, coalesced)
//   4 x independent LDG.128 (64B contiguous per thread) -> MLP ~5 front-batched
//   4 x RED.E.ADD.F32.V4 to one 64B output line (L2-resident, 6.4 MB total)
// edge_w is streamed exactly once -> __ldcs (evict-first) so L2 stays dedicated
// to the atomic destination lines.
__global__ void __launch_bounds__(256)
spmm_scatter_kernel(const int* __restrict__ src,
                    const float4* __restrict__ w4,   // [E*4] float4
                    float4* __restrict__ out4,       // [N*4] float4
                    int E)
{
    int e = blockIdx.x * blockDim.x + threadIdx.x;
    if (e >= E) return;

    int s = __ldg(&src[e]);

    const float4* row = w4 + (size_t)e * 4;
    // 4 independent loads — ptxas front-batches these (MLP 4-5)
    float4 v0 = __ldcs(row + 0);
    float4 v1 = __ldcs(row + 1);
    float4 v2 = __ldcs(row + 2);
    float4 v3 = __ldcs(row + 3);

    float4* o = out4 + (size_t)s * 4;
    atomicAdd(o + 0, v0);
    atomicAdd(o + 1, v1);
    atomicAdd(o + 2, v2);
    atomicAdd(o + 3, v3);
}

extern "C" void kernel_launch(void* const* d_in, const int* in_sizes, int n_in,
                              void* d_out, int out_size)
{
    const int E = 3200000;

    const int*   edge   = (const int*)d_in[0];   // edge[0] = src, first E ints
    const float* edge_w = (const float*)d_in[1];

    // d_out poisoned to 0xAA -> zero it (memset node is graph-capturable).
    cudaMemsetAsync(d_out, 0, (size_t)out_size * sizeof(float), 0);

    int threads = 256;
    int blocks  = (E + threads - 1) / threads;

    spmm_scatter_kernel<<<blocks, threads>>>(
        edge,
        (const float4*)edge_w,
        (float4*)d_out,
        E);
}

// round 4
// speedup vs baseline: 1.5778x; 1.5778x over previous
#include <cuda_runtime.h>
#include <cuda_bf16.h>

// Thread-per-quad layout (R1's coalescing: warp loads 32 consecutive float4s
// = 4 × 128B lines per LDG), but 4 quads per thread, grid-strided by the total
// thread count so each batch stays perfectly coalesced.
// All 8 loads (4 src + 4 w) are issued front-batched -> MLP_p1 ~ 8, hiding
// DRAM latency. REDs are no-return (fire-and-forget) so they add no exposure.
//
// Sizes are fixed: E = 3.2M edges, F = 16 floats -> 12.8M quads.
// 3.2M threads x 4 quads each, exact (no bounds checks).

#define NUM_QUADS  (3200000 * 4)
#define THREADS_PB 256
#define QUADS_PER_THREAD 4
#define TOTAL_THREADS (NUM_QUADS / QUADS_PER_THREAD)   // 3,200,000
#define NUM_BLOCKS (TOTAL_THREADS / THREADS_PB)        // 12,500

__global__ void __launch_bounds__(THREADS_PB)
spmm_scatter_kernel(const int* __restrict__ src,
                    const float4* __restrict__ w4,   // [E*4] float4
                    float4* __restrict__ out4)       // [N*4] float4
{
    const int tid = blockIdx.x * THREADS_PB + threadIdx.x;
    const int S   = TOTAL_THREADS;

    const int i0 = tid;
    const int i1 = tid + S;
    const int i2 = tid + 2 * S;
    const int i3 = tid + 3 * S;

    // Front-batched independent loads (ptxas hoists these together).
    int s0 = __ldg(&src[i0 >> 2]);
    int s1 = __ldg(&src[i1 >> 2]);
    int s2 = __ldg(&src[i2 >> 2]);
    int s3 = __ldg(&src[i3 >> 2]);

    float4 v0 = __ldcs(&w4[i0]);   // evict-first: edge_w streams once,
    float4 v1 = __ldcs(&w4[i1]);   // keep L2 for the atomic destinations
    float4 v2 = __ldcs(&w4[i2]);
    float4 v3 = __ldcs(&w4[i3]);

    atomicAdd(&out4[((size_t)s0 << 2) + (i0 & 3)], v0);
    atomicAdd(&out4[((size_t)s1 << 2) + (i1 & 3)], v1);
    atomicAdd(&out4[((size_t)s2 << 2) + (i2 & 3)], v2);
    atomicAdd(&out4[((size_t)s3 << 2) + (i3 & 3)], v3);
}

extern "C" void kernel_launch(void* const* d_in, const int* in_sizes, int n_in,
                              void* d_out, int out_size)
{
    const int*   edge   = (const int*)d_in[0];   // edge[0] = src, first E ints
    const float* edge_w = (const float*)d_in[1];

    // d_out poisoned to 0xAA -> zero it (memset node is graph-capturable).
    cudaMemsetAsync(d_out, 0, (size_t)out_size * sizeof(float), 0);

    spmm_scatter_kernel<<<NUM_BLOCKS, THREADS_PB>>>(
        edge,
        (const float4*)edge_w,
        (float4*)d_out);
}